// round 14
// baseline (speedup 1.0000x reference)
#include <cuda_runtime.h>

// WindowEmbedding forward: out[b, t, k*D + d] = (t-k >= 0) ? in[b, t-k, d] : 0
// B=16, T=2048, D=256, W=7.
//
// FINAL (R13 = R9, best measured: kernel 39.55us, DRAM 66.8%, rel_err 0).
//
// Convergence evidence — eight structural variants all pinned at the same
// ~5.2-5.3 TB/s write-dominated DRAM plateau (kernel 39.6-44.3us), with no
// SM-side resource above 84%:
//   R2  direct STG.128, MLP=8          39.74us   R7  direct STG.256   42.53us
//   R3  smem + __stcs                  40.64us   R10 persistent grid  44.29us
//   R4  smem + plain STG               41.38us   R12 2x coarsened     40.48us
//   R6  TMA bulk store (LSU bypass)    40.83us   R9/R11 (this)        39.55us
// The output is a definitional 7x data expansion: 235 MB of stores is the
// workload. Reads stay L2-resident (~0 DRAM reads). ~39.5us is the floor.
//
// Structure: one 448-thread block per 8 consecutive t values; thread
// (k, d4) moves float4 in[b, t-k, d4] -> out[b, t, k*64+d4] for 8 t's,
// all 8 loads batched before 8 streaming stores (__stcs keeps the 7x-read
// input resident in L2 and was measurably >= plain/wt stores).

#define B_DIM 16
#define T_DIM 2048
#define D_DIM 256
#define W_DIM 7

#define D4 (D_DIM / 4)          // 64 float4 per input row
#define SLICE4 (W_DIM * D4)     // 448 float4 per output row
#define TILE_T 8                // t-values per thread

__global__ __launch_bounds__(SLICE4) void window_embed_kernel(
    const float4* __restrict__ in,   // [B, T, 64] float4
    float4* __restrict__ out)        // [B, T, 448] float4
{
    const int bt0 = blockIdx.x * TILE_T;     // base (b*T + t0), t0 multiple of 8
    const int t0  = bt0 & (T_DIM - 1);
    const int tid = threadIdx.x;             // 0..447
    const int k   = tid >> 6;                // shift 0..6
    const int d4  = tid & 63;                // float4 column

    // Signed 32-bit offsets: max magnitude ~14.7M; sign-extension handles the
    // (rare) bt0 - k < 0 base in block 0 (never dereferenced there).
    const int soff = (bt0 - k) * D4 + d4;
    const int doff = bt0 * SLICE4 + tid;

    const float4* src = in  + soff;
    float4*       dst = out + doff;

    float4 v[TILE_T];

    if (t0 != 0) {
        // Fast path (4080/4096 blocks): t0 >= 8 > k, all sources valid.
        #pragma unroll
        for (int j = 0; j < TILE_T; j++)
            v[j] = src[j * D4];
        #pragma unroll
        for (int j = 0; j < TILE_T; j++)
            __stcs(&dst[j * SLICE4], v[j]);
    } else {
        // t0 == 0: zero-fill where t - k < 0.
        #pragma unroll
        for (int j = 0; j < TILE_T; j++) {
            const int ts = j - k;
            v[j] = (ts >= 0) ? src[j * D4] : make_float4(0.f, 0.f, 0.f, 0.f);
        }
        #pragma unroll
        for (int j = 0; j < TILE_T; j++)
            __stcs(&dst[j * SLICE4], v[j]);
    }
}

extern "C" void kernel_launch(void* const* d_in, const int* in_sizes, int n_in,
                              void* d_out, int out_size)
{
    const float4* in = (const float4*)d_in[0];
    float4* out = (float4*)d_out;

    dim3 grid(B_DIM * T_DIM / TILE_T);   // 4096
    dim3 block(SLICE4);                  // 448
    window_embed_kernel<<<grid, block>>>(in, out);
}

// round 15
// speedup vs baseline: 1.0008x; 1.0008x over previous
#include <cuda_runtime.h>

// WindowEmbedding forward: out[b, t, k*D + d] = (t-k >= 0) ? in[b, t-k, d] : 0
// B=16, T=2048, D=256, W=7.
// R14: true-MLP=8 probe. All prior rounds compiled at regs=32, which cannot
// hold 8 in-flight float4 (32 data regs + addressing) — ptxas was sinking
// stores between loads, so the designed MLP=8 batch never existed in SASS.
// __launch_bounds__(448, 3) raises the reg budget to ~48 so the batch
// compiles as written (occupancy 4->3 blocks/SM, but 2x per-thread MLP).
// Flat result = DRAM pure-write ceiling fully confirmed; R9 stands final.

#define B_DIM 16
#define T_DIM 2048
#define D_DIM 256
#define W_DIM 7

#define D4 (D_DIM / 4)          // 64 float4 per input row
#define SLICE4 (W_DIM * D4)     // 448 float4 per output row
#define TILE_T 8                // t-values per thread

__global__ __launch_bounds__(SLICE4, 3) void window_embed_kernel(
    const float4* __restrict__ in,   // [B, T, 64] float4
    float4* __restrict__ out)        // [B, T, 448] float4
{
    const int bt0 = blockIdx.x * TILE_T;     // base (b*T + t0), t0 multiple of 8
    const int t0  = bt0 & (T_DIM - 1);
    const int tid = threadIdx.x;             // 0..447
    const int k   = tid >> 6;                // shift 0..6
    const int d4  = tid & 63;                // float4 column

    // Signed 32-bit offsets; sign-extension handles bt0 - k < 0 in block 0.
    const float4* src = in  + ((bt0 - k) * D4 + d4);
    float4*       dst = out + (bt0 * SLICE4 + tid);

    float4 v[TILE_T];

    if (t0 != 0) {
        // Fast path (4080/4096 blocks): all 8 loads issued back-to-back
        // (now actually possible with the 48-reg budget), then 8 stores.
        #pragma unroll
        for (int j = 0; j < TILE_T; j++)
            v[j] = src[j * D4];
        #pragma unroll
        for (int j = 0; j < TILE_T; j++)
            __stcs(&dst[j * SLICE4], v[j]);
    } else {
        // t0 == 0: zero-fill where t - k < 0.
        #pragma unroll
        for (int j = 0; j < TILE_T; j++) {
            const int ts = j - k;
            v[j] = (ts >= 0) ? src[j * D4] : make_float4(0.f, 0.f, 0.f, 0.f);
        }
        #pragma unroll
        for (int j = 0; j < TILE_T; j++)
            __stcs(&dst[j * SLICE4], v[j]);
    }
}

extern "C" void kernel_launch(void* const* d_in, const int* in_sizes, int n_in,
                              void* d_out, int out_size)
{
    const float4* in = (const float4*)d_in[0];
    float4* out = (float4*)d_out;

    dim3 grid(B_DIM * T_DIM / TILE_T);   // 4096
    dim3 block(SLICE4);                  // 448
    window_embed_kernel<<<grid, block>>>(in, out);
}